// round 11
// baseline (speedup 1.0000x reference)
#include <cuda_runtime.h>
#include <cuda_bf16.h>

// Problem shapes (fixed for this registry entry)
#define BS  4
#define NPT 8192
#define CH  64
#define MPT 4096
#define KNN 32
#define R2C  0.04f
#define R2LO 0.03999996f   // R2*(1-1e-6): cheap <= R2LO  => faithful <= R2
#define R2HI 0.04000004f   // R2*(1+1e-6): cheap >  R2HI  => faithful >  R2

#define FPS_T 1024
#define PPT   (NPT / FPS_T)   // 8 points per thread
#define BQW   8               // children (warps) per ball-query block
#define FULLM 0xffffffffu

typedef unsigned long long u64;

// Scratch: transposed feats (bs, n, c). 8 MB.
__device__ float g_feats_t[(size_t)BS * NPT * CH];

// ---------------------------------------------------------------------------
// Faithfully-rounded dx^2+dy^2+dz^2 via error-free transforms (f32 FMA pipe).
// Bit-exact selection behavior established in R3 (rel_err == 0).
// ---------------------------------------------------------------------------
__device__ __forceinline__ float dist2_acc(float dx, float dy, float dz)
{
    const float p1 = __fmul_rn(dx, dx);
    const float e1 = __fmaf_rn(dx, dx, -p1);
    const float p2 = __fmul_rn(dy, dy);
    const float e2 = __fmaf_rn(dy, dy, -p2);
    const float p3 = __fmul_rn(dz, dz);
    const float e3 = __fmaf_rn(dz, dz, -p3);
    const float s1  = __fadd_rn(p1, p2);
    const float b1  = __fsub_rn(s1, p1);
    const float t1  = __fadd_rn(__fsub_rn(p1, __fsub_rn(s1, b1)), __fsub_rn(p2, b1));
    const float s2  = __fadd_rn(s1, p3);
    const float b2  = __fsub_rn(s2, s1);
    const float t2  = __fadd_rn(__fsub_rn(s1, __fsub_rn(s2, b2)), __fsub_rn(p3, b2));
    const float err = __fadd_rn(__fadd_rn(__fadd_rn(e1, e2), e3), __fadd_rn(t1, t2));
    return __fadd_rn(s2, err);
}

// packed argmax key: high 32 = d2 bits (d2 >= 0 so order-preserving),
// low 32 = ~idx  =>  max key == max d2 with lowest-index tie-break.
__device__ __forceinline__ u64 pack_key(float v, int idx)
{
    return ((u64)__float_as_uint(v) << 32) | (unsigned)(~idx);
}

// ---------------------------------------------------------------------------
// FPS: one CTA per batch.
//  - branch-free steady state: all 8 cheap filters computed unconditionally,
//    pass bits gathered in a register mask, ONE guard branch to the rare path
//  - tight relative filter (R9): cheap <= md*(1+1e-6), certified vs EFT
//  - dirty-warp-only stage1; redux.sync argmax; coords travel in smem slots
// ---------------------------------------------------------------------------
__global__ void __launch_bounds__(FPS_T, 1)
fps_kernel(const float* __restrict__ xyz, float* __restrict__ child_xyz)
{
    __shared__ u64   skey[2][32];
    __shared__ float sx[2][32], sy[2][32], sz[2][32];

    const int b    = blockIdx.x;
    const int tid  = threadIdx.x;
    const int lane = tid & 31;
    const int wid  = tid >> 5;

    const float* __restrict__ X  = xyz + (size_t)b * NPT * 3;
    float* __restrict__       OX = child_xyz + (size_t)b * MPT * 3;

    float px[PPT], py[PPT], pz[PPT], md[PPT];
#pragma unroll
    for (int k = 0; k < PPT; k++) {
        const int j = tid + k * FPS_T;
        px[k] = X[3 * j + 0];
        py[k] = X[3 * j + 1];
        pz[k] = X[3 * j + 2];
        md[k] = 1e10f;
    }
    // thread-best cache: key + that point's coords (all md equal -> k=0)
    u64   ckey = pack_key(1e10f, tid);
    float ax = px[0], ay = py[0], az = pz[0];
    // warp-best cache (held by all lanes; lane0 reposts it each iter)
    u64   wkey = 0;
    float wx = 0.f, wy = 0.f, wz = 0.f;

    float cx = X[0], cy = X[1], cz = X[2];

    for (int it = 0; it < MPT; it++) {
        if (tid == 0) {
            OX[3 * it + 0] = cx;
            OX[3 * it + 1] = cy;
            OX[3 * it + 2] = cz;
        }

        // ---- branch-free filter pass over all 8 slots ----
        unsigned passmask = 0;
#pragma unroll
        for (int k = 0; k < PPT; k++) {
            const float dx = __fsub_rn(px[k], cx);
            const float dy = __fsub_rn(py[k], cy);
            const float dz = __fsub_rn(pz[k], cz);
            const float cheap = __fmaf_rn(dz, dz, __fmaf_rn(dy, dy,
                                          __fmul_rn(dx, dx)));
            // certified filter: pass iff faithful d2 could be < md[k]
            if (cheap <= __fmul_rn(md[k], 1.000001f))
                passmask |= 1u << k;                 // FSETP + LOP, no branch
        }

        // ---- rare path: EFT only for flagged slots ----
        bool updated = false;
        if (passmask) {
#pragma unroll
            for (int k = 0; k < PPT; k++) {
                if (passmask & (1u << k)) {
                    const float dx = __fsub_rn(px[k], cx);
                    const float dy = __fsub_rn(py[k], cy);
                    const float dz = __fsub_rn(pz[k], cz);
                    const float d2 = dist2_acc(dx, dy, dz);
                    if (d2 < md[k]) { md[k] = d2; updated = true; }
                }
            }
        }

        // stage1: only dirty warps re-reduce (md monotone non-increasing)
        const unsigned dirty = __ballot_sync(FULLM, updated);
        if (dirty) {
            if (updated) {                      // refresh thread cache
                float bv = md[0]; int bi = tid;
                float tx = px[0], ty = py[0], tz = pz[0];
#pragma unroll
                for (int k = 1; k < PPT; k++)
                    if (md[k] > bv) {
                        bv = md[k]; bi = tid + k * FPS_T;
                        tx = px[k]; ty = py[k]; tz = pz[k];
                    }
                ckey = pack_key(bv, bi);
                ax = tx; ay = ty; az = tz;
            }
            const unsigned hi = (unsigned)(ckey >> 32);
            const unsigned lo = (unsigned)ckey;
            const unsigned mh = __reduce_max_sync(FULLM, hi);
            const unsigned ml = __reduce_max_sync(FULLM, (hi == mh) ? lo : 0u);
            wkey = ((u64)mh << 32) | ml;
            const bool win = (hi == mh) && (lo == ml);   // unique lane
            const int  wl  = __ffs(__ballot_sync(FULLM, win)) - 1;
            wx = __shfl_sync(FULLM, ax, wl);
            wy = __shfl_sync(FULLM, ay, wl);
            wz = __shfl_sync(FULLM, az, wl);
        }
        const int p = it & 1;
        if (lane == 0) {
            skey[p][wid] = wkey;
            sx[p][wid] = wx; sy[p][wid] = wy; sz[p][wid] = wz;
        }
        __syncthreads();

        // stage2: every warp reduces the 32 per-warp slots via redux
        const u64 k2       = skey[p][lane];
        const unsigned hi2 = (unsigned)(k2 >> 32);
        const unsigned lo2 = (unsigned)k2;
        const unsigned mh2 = __reduce_max_sync(FULLM, hi2);
        const unsigned ml2 = __reduce_max_sync(FULLM, (hi2 == mh2) ? lo2 : 0u);
        const bool match   = (hi2 == mh2) && (lo2 == ml2);
        const int  s       = __ffs(__ballot_sync(FULLM, match)) - 1;
        cx = sx[p][s]; cy = sy[p][s]; cz = sz[p][s];      // broadcast LDS
    }
}

// ---------------------------------------------------------------------------
// Transpose feats (bs, C, N) -> g_feats_t (bs, N, C), tiled 32x32.
// ---------------------------------------------------------------------------
__global__ void transpose_kernel(const float* __restrict__ feats)
{
    __shared__ float tile[32][33];
    const int b  = blockIdx.z;
    const int n0 = blockIdx.x * 32;
    const int c0 = blockIdx.y * 32;
    const int tx = threadIdx.x;
    const int ty = threadIdx.y;

    const float* __restrict__ F  = feats + (size_t)b * CH * NPT;
    float* __restrict__       FT = g_feats_t + (size_t)b * NPT * CH;

#pragma unroll
    for (int r = ty; r < 32; r += 8)
        tile[r][tx] = F[(size_t)(c0 + r) * NPT + n0 + tx];
    __syncthreads();
#pragma unroll
    for (int r = ty; r < 32; r += 8)
        FT[(size_t)(n0 + r) * CH + c0 + tx] = tile[tx][r];
}

// ---------------------------------------------------------------------------
// Fused ball query (first-K-within-radius, ascending index) + grouped max.
// Certified cheap filter: EFT only in the 1e-6-wide boundary band.
// ---------------------------------------------------------------------------
__global__ void __launch_bounds__(BQW * 32)
bq_group_kernel(const float* __restrict__ xyz,
                const float* __restrict__ child_xyz,
                float* __restrict__ out_feats)
{
    __shared__ int   nidx[BQW][KNN];
    __shared__ float sfeat[CH][BQW];

    const int b    = blockIdx.y;
    const int j0   = blockIdx.x * BQW;
    const int w    = threadIdx.x >> 5;
    const int lane = threadIdx.x & 31;
    const int j    = j0 + w;

    const float* __restrict__ X = xyz + (size_t)b * NPT * 3;
    const float cx = child_xyz[((size_t)b * MPT + j) * 3 + 0];
    const float cy = child_xyz[((size_t)b * MPT + j) * 3 + 1];
    const float cz = child_xyz[((size_t)b * MPT + j) * 3 + 2];

    int cnt = 0;
    for (int base = 0; base < NPT; base += 32) {
        const int p = base + lane;
        const float dx = __fsub_rn(X[3 * p + 0], cx);
        const float dy = __fsub_rn(X[3 * p + 1], cy);
        const float dz = __fsub_rn(X[3 * p + 2], cz);
        const float cheap = __fmaf_rn(dz, dz, __fmaf_rn(dy, dy,
                                      __fmul_rn(dx, dx)));
        bool in = (cheap <= R2LO);                         // certified in
        if (cheap > R2LO && cheap <= R2HI)                 // boundary band
            in = (dist2_acc(dx, dy, dz) <= R2C);
        const unsigned mask = __ballot_sync(FULLM, in);
        const int pos = cnt + __popc(mask & ((1u << lane) - 1u));
        if (in && pos < KNN) nidx[w][pos] = p;
        cnt += __popc(mask);
        if (cnt >= KNN) break;   // warp-uniform
    }
    if (cnt == 0) { if (lane == 0) nidx[w][0] = 0; cnt = 1; }
    const int kmax = cnt < KNN ? cnt : KNN;
    __syncwarp();

    const float* __restrict__ FT = g_feats_t + (size_t)b * NPT * CH;
    float m0 = -3.4e38f, m1 = -3.4e38f;
    for (int k = 0; k < kmax; k++) {
        const int p = nidx[w][k];                 // LDS broadcast
        const float2 v = *(const float2*)(FT + (size_t)p * CH + lane * 2);
        m0 = fmaxf(m0, v.x);
        m1 = fmaxf(m1, v.y);
    }
    sfeat[lane * 2 + 0][w] = m0;
    sfeat[lane * 2 + 1][w] = m1;
    __syncthreads();

    // coalesced staged store of (C x BQW) block
    for (int t = threadIdx.x; t < CH * BQW; t += BQW * 32) {
        const int c  = t >> 3;          // / BQW
        const int jj = t & (BQW - 1);
        out_feats[((size_t)b * CH + c) * MPT + j0 + jj] = sfeat[c][jj];
    }
}

// ---------------------------------------------------------------------------
extern "C" void kernel_launch(void* const* d_in, const int* in_sizes, int n_in,
                              void* d_out, int out_size)
{
    const float* xyz   = (const float*)d_in[0];
    const float* feats = (const float*)d_in[1];

    float* out         = (float*)d_out;
    float* child_xyz   = out;                              // (bs, m, 3)
    float* child_feats = out + (size_t)BS * MPT * 3;       // (bs, C, m)

    transpose_kernel<<<dim3(NPT / 32, CH / 32, BS), dim3(32, 8)>>>(feats);
    fps_kernel<<<BS, FPS_T>>>(xyz, child_xyz);
    bq_group_kernel<<<dim3(MPT / BQW, BS), BQW * 32>>>(xyz, child_xyz, child_feats);
}

// round 13
// speedup vs baseline: 1.1763x; 1.1763x over previous
#include <cuda_runtime.h>
#include <cuda_bf16.h>

// Problem shapes (fixed for this registry entry)
#define BS  4
#define NPT 8192
#define CH  64
#define MPT 4096
#define KNN 32
#define R2C  0.04f
#define R2LO 0.03999996f   // R2*(1-1e-6): cheap <= R2LO  => faithful <= R2
#define R2HI 0.04000004f   // R2*(1+1e-6): cheap >  R2HI  => faithful >  R2

#define FPS_T 1024
#define PPT   (NPT / FPS_T)   // 8 points per thread (one spatial group)
#define BQW   8               // children (warps) per ball-query block
#define FULLM 0xffffffffu
#define NBIN  4096             // 16^3 Morton bins

typedef unsigned long long u64;

// Scratch
__device__ float  g_feats_t[(size_t)BS * NPT * CH];   // transposed feats, 8 MB
__device__ float4 g_sorted[(size_t)BS * NPT];         // Morton-sorted xyz+idx
__device__ unsigned g_code[(size_t)BS * NPT];         // per-point bin code

// ---------------------------------------------------------------------------
// Faithfully-rounded dx^2+dy^2+dz^2 via error-free transforms (f32 FMA pipe).
// Bit-exact selection behavior established in R3 (rel_err == 0).
// ---------------------------------------------------------------------------
__device__ __forceinline__ float dist2_acc(float dx, float dy, float dz)
{
    const float p1 = __fmul_rn(dx, dx);
    const float e1 = __fmaf_rn(dx, dx, -p1);
    const float p2 = __fmul_rn(dy, dy);
    const float e2 = __fmaf_rn(dy, dy, -p2);
    const float p3 = __fmul_rn(dz, dz);
    const float e3 = __fmaf_rn(dz, dz, -p3);
    const float s1  = __fadd_rn(p1, p2);
    const float b1  = __fsub_rn(s1, p1);
    const float t1  = __fadd_rn(__fsub_rn(p1, __fsub_rn(s1, b1)), __fsub_rn(p2, b1));
    const float s2  = __fadd_rn(s1, p3);
    const float b2  = __fsub_rn(s2, s1);
    const float t2  = __fadd_rn(__fsub_rn(s1, __fsub_rn(s2, b2)), __fsub_rn(p3, b2));
    const float err = __fadd_rn(__fadd_rn(__fadd_rn(e1, e2), e3), __fadd_rn(t1, t2));
    return __fadd_rn(s2, err);
}

__device__ __forceinline__ float cheap_d2(float dx, float dy, float dz)
{
    return __fmaf_rn(dz, dz, __fmaf_rn(dy, dy, __fmul_rn(dx, dx)));
}

// packed argmax key: high 32 = d2 bits (d2 >= 0 so order-preserving),
// low 32 = ~idx  =>  max key == max d2 with lowest-index tie-break.
__device__ __forceinline__ u64 pack_key(float v, unsigned idx)
{
    return ((u64)__float_as_uint(v) << 32) | (unsigned)(~idx);
}

// 4-bit spread for Morton: bit i -> bit 3i
__device__ __forceinline__ unsigned spread4(unsigned v)
{
    return (v & 1u) | ((v & 2u) << 2) | ((v & 4u) << 4) | ((v & 8u) << 6);
}
__device__ __forceinline__ unsigned morton12(float x, float y, float z)
{
    int qx = (int)floorf((x + 4.0f) * 2.0f);
    int qy = (int)floorf((y + 4.0f) * 2.0f);
    int qz = (int)floorf((z + 4.0f) * 2.0f);
    qx = min(15, max(0, qx)); qy = min(15, max(0, qy)); qz = min(15, max(0, qz));
    return spread4((unsigned)qx) | (spread4((unsigned)qy) << 1)
         | (spread4((unsigned)qz) << 2);
}

// ---------------------------------------------------------------------------
// Counting sort by 12-bit Morton code. One CTA per batch.
// Within-bin order is arbitrary (atomics) — grouping only affects pruning,
// never the FPS selection, so the final output is deterministic.
// ---------------------------------------------------------------------------
__global__ void __launch_bounds__(FPS_T, 1)
sort_kernel(const float* __restrict__ xyz)
{
    __shared__ unsigned hist[NBIN];
    __shared__ unsigned warpsum[32];

    const int b    = blockIdx.x;
    const int tid  = threadIdx.x;
    const int lane = tid & 31;
    const int wid  = tid >> 5;

    const float* __restrict__ X = xyz + (size_t)b * NPT * 3;

#pragma unroll
    for (int k = 0; k < NBIN / FPS_T; k++) hist[tid + k * FPS_T] = 0u;
    __syncthreads();

    // pass 1: codes + histogram
#pragma unroll
    for (int k = 0; k < PPT; k++) {
        const int j = tid + k * FPS_T;
        const unsigned code = morton12(X[3 * j], X[3 * j + 1], X[3 * j + 2]);
        g_code[(size_t)b * NPT + j] = code;
        atomicAdd(&hist[code], 1u);
    }
    __syncthreads();

    // exclusive prefix sum over 4096 bins (4 per thread)
    const unsigned c0 = hist[4 * tid + 0];
    const unsigned c1 = hist[4 * tid + 1];
    const unsigned c2 = hist[4 * tid + 2];
    const unsigned c3 = hist[4 * tid + 3];
    const unsigned tot = c0 + c1 + c2 + c3;
    unsigned incl = tot;
#pragma unroll
    for (int off = 1; off < 32; off <<= 1) {
        const unsigned n = __shfl_up_sync(FULLM, incl, off);
        if (lane >= off) incl += n;
    }
    if (lane == 31) warpsum[wid] = incl;
    __syncthreads();
    if (wid == 0) {
        const unsigned v = warpsum[lane];
        unsigned i2 = v;
#pragma unroll
        for (int off = 1; off < 32; off <<= 1) {
            const unsigned n = __shfl_up_sync(FULLM, i2, off);
            if (lane >= off) i2 += n;
        }
        warpsum[lane] = i2 - v;          // exclusive warp base
    }
    __syncthreads();
    unsigned base = warpsum[wid] + incl - tot;
    hist[4 * tid + 0] = base;  base += c0;
    hist[4 * tid + 1] = base;  base += c1;
    hist[4 * tid + 2] = base;  base += c2;
    hist[4 * tid + 3] = base;
    __syncthreads();

    // pass 2: scatter
#pragma unroll
    for (int k = 0; k < PPT; k++) {
        const int j = tid + k * FPS_T;
        const unsigned code = g_code[(size_t)b * NPT + j];
        const unsigned pos  = atomicAdd(&hist[code], 1u);
        float4 v;
        v.x = X[3 * j];  v.y = X[3 * j + 1];  v.z = X[3 * j + 2];
        v.w = __uint_as_float((unsigned)j);
        g_sorted[(size_t)b * NPT + pos] = v;
    }
}

// ---------------------------------------------------------------------------
// FPS: one CTA per batch, triangle-inequality group pruning.
//  - thread owns 8 consecutive Morton-sorted points: centroid g, radius rt
//  - steady state: ONE cheap d2(c,g) vs S2; skip certifies no md update
//  - unpruned path: R9 per-slot certified filter + EFT (bit-exact)
//  - dirty-warp stage1 + redux argmax + coords-in-slots (R9 tail)
// ---------------------------------------------------------------------------
__global__ void __launch_bounds__(FPS_T, 1)
fps_kernel(float* __restrict__ child_xyz)
{
    __shared__ u64   skey[2][32];
    __shared__ float sx[2][32], sy[2][32], sz[2][32];

    const int b    = blockIdx.x;
    const int tid  = threadIdx.x;
    const int lane = tid & 31;
    const int wid  = tid >> 5;

    const float4* __restrict__ SP = g_sorted + (size_t)b * NPT;
    const float*  __restrict__ SPF = (const float*)SP;
    float* __restrict__        OX = child_xyz + (size_t)b * MPT * 3;

    // ---- init: group stats + md + thread-best cache ----
    float md[PPT];
    float gx = 0.f, gy = 0.f, gz = 0.f;
    {
#pragma unroll
        for (int k = 0; k < PPT; k++) {
            const float4 p = __ldg(&SP[tid * PPT + k]);
            gx += p.x; gy += p.y; gz += p.z;
            md[k] = 1e10f;
        }
        gx *= 0.125f; gy *= 0.125f; gz *= 0.125f;
    }
    float r2m = 0.f;
    u64   ckey = 0;
    float ax = 0.f, ay = 0.f, az = 0.f;
    {
#pragma unroll
        for (int k = 0; k < PPT; k++) {
            const float4 p = __ldg(&SP[tid * PPT + k]);
            const float d2 = cheap_d2(p.x - gx, p.y - gy, p.z - gz);
            r2m = fmaxf(r2m, d2);
            const u64 key = pack_key(1e10f, __float_as_uint(p.w));
            if (key > ckey) { ckey = key; ax = p.x; ay = p.y; az = p.z; }
        }
    }
    const float rt = __fsqrt_ru(__fmul_ru(r2m, 1.00001f));  // certified ub
    float Mk = 1e10f;
    float S  = __fadd_ru(__fsqrt_ru(Mk), rt);
    float S2 = __fmul_ru(__fmul_ru(S, S), 1.00001f);

    // warp-best cache (held by all lanes; lane0 reposts it each iter)
    u64   wkey = 0;
    float wx = 0.f, wy = 0.f, wz = 0.f;

    // first center = original point 0: each thread scans its slots; the
    // owner posts coords to smem (one-time).
    float cx, cy, cz;
    {
        __shared__ float c0[3];
#pragma unroll
        for (int k = 0; k < PPT; k++) {
            const float4 p = __ldg(&SP[tid * PPT + k]);
            if (__float_as_uint(p.w) == 0u) {
                c0[0] = p.x; c0[1] = p.y; c0[2] = p.z;
            }
        }
        __syncthreads();
        cx = c0[0]; cy = c0[1]; cz = c0[2];
    }

    for (int it = 0; it < MPT; it++) {
        if (tid == 0) {
            OX[3 * it + 0] = cx;
            OX[3 * it + 1] = cy;
            OX[3 * it + 2] = cz;
        }

        // ---- group prune test (steady state: this is ALL the work) ----
        const float d2g = cheap_d2(gx - cx, gy - cy, gz - cz);
        bool updated = false;
        if (d2g <= S2) {                      // group cannot be pruned
#pragma unroll
            for (int k = 0; k < PPT; k++) {
                const float4 p = __ldg(&SP[tid * PPT + k]);
                const float dx = __fsub_rn(p.x, cx);
                const float dy = __fsub_rn(p.y, cy);
                const float dz = __fsub_rn(p.z, cz);
                const float cheap = cheap_d2(dx, dy, dz);
                if (cheap <= __fmul_rn(md[k], 1.000001f)) {   // R9 filter
                    const float d2 = dist2_acc(dx, dy, dz);
                    if (d2 < md[k]) { md[k] = d2; updated = true; }
                }
            }
        }
        if (updated) {                        // rare: refresh caches
            float bv = md[0];
#pragma unroll
            for (int k = 1; k < PPT; k++)
                if (md[k] > bv) bv = md[k];
            // exact key needs original indices: re-scan with tie-break
            u64 nk = 0; int bs = 0;
#pragma unroll
            for (int k = 0; k < PPT; k++) {
                const unsigned oid =
                    __float_as_uint(__ldg(&SPF[4 * (tid * PPT + k) + 3]));
                const u64 key = pack_key(md[k], oid);
                if (key > nk) { nk = key; bs = k; }
            }
            ckey = nk;
            const float4 p = __ldg(&SP[tid * PPT + bs]);
            ax = p.x; ay = p.y; az = p.z;
            Mk = bv;
            S  = __fadd_ru(__fsqrt_ru(Mk), rt);
            S2 = __fmul_ru(__fmul_ru(S, S), 1.00001f);
        }

        // stage1: only dirty warps re-reduce (md monotone non-increasing)
        const unsigned dirty = __ballot_sync(FULLM, updated);
        if (dirty) {
            const unsigned hi = (unsigned)(ckey >> 32);
            const unsigned lo = (unsigned)ckey;
            const unsigned mh = __reduce_max_sync(FULLM, hi);
            const unsigned ml = __reduce_max_sync(FULLM, (hi == mh) ? lo : 0u);
            wkey = ((u64)mh << 32) | ml;
            const bool win = (hi == mh) && (lo == ml);   // unique lane
            const int  wl  = __ffs(__ballot_sync(FULLM, win)) - 1;
            wx = __shfl_sync(FULLM, ax, wl);
            wy = __shfl_sync(FULLM, ay, wl);
            wz = __shfl_sync(FULLM, az, wl);
        }
        const int p = it & 1;
        if (lane == 0) {
            skey[p][wid] = wkey;
            sx[p][wid] = wx; sy[p][wid] = wy; sz[p][wid] = wz;
        }
        __syncthreads();

        // stage2: every warp reduces the 32 per-warp slots via redux
        const u64 k2       = skey[p][lane];
        const unsigned hi2 = (unsigned)(k2 >> 32);
        const unsigned lo2 = (unsigned)k2;
        const unsigned mh2 = __reduce_max_sync(FULLM, hi2);
        const unsigned ml2 = __reduce_max_sync(FULLM, (hi2 == mh2) ? lo2 : 0u);
        const bool match   = (hi2 == mh2) && (lo2 == ml2);
        const int  s       = __ffs(__ballot_sync(FULLM, match)) - 1;
        cx = sx[p][s]; cy = sy[p][s]; cz = sz[p][s];      // broadcast LDS
    }
}

// ---------------------------------------------------------------------------
// Transpose feats (bs, C, N) -> g_feats_t (bs, N, C), tiled 32x32.
// ---------------------------------------------------------------------------
__global__ void transpose_kernel(const float* __restrict__ feats)
{
    __shared__ float tile[32][33];
    const int b  = blockIdx.z;
    const int n0 = blockIdx.x * 32;
    const int c0 = blockIdx.y * 32;
    const int tx = threadIdx.x;
    const int ty = threadIdx.y;

    const float* __restrict__ F  = feats + (size_t)b * CH * NPT;
    float* __restrict__       FT = g_feats_t + (size_t)b * NPT * CH;

#pragma unroll
    for (int r = ty; r < 32; r += 8)
        tile[r][tx] = F[(size_t)(c0 + r) * NPT + n0 + tx];
    __syncthreads();
#pragma unroll
    for (int r = ty; r < 32; r += 8)
        FT[(size_t)(n0 + r) * CH + c0 + tx] = tile[tx][r];
}

// ---------------------------------------------------------------------------
// Fused ball query (first-K-within-radius, ascending index) + grouped max.
// Certified cheap filter: EFT only in the 1e-6-wide boundary band.
// ---------------------------------------------------------------------------
__global__ void __launch_bounds__(BQW * 32)
bq_group_kernel(const float* __restrict__ xyz,
                const float* __restrict__ child_xyz,
                float* __restrict__ out_feats)
{
    __shared__ int   nidx[BQW][KNN];
    __shared__ float sfeat[CH][BQW];

    const int b    = blockIdx.y;
    const int j0   = blockIdx.x * BQW;
    const int w    = threadIdx.x >> 5;
    const int lane = threadIdx.x & 31;
    const int j    = j0 + w;

    const float* __restrict__ X = xyz + (size_t)b * NPT * 3;
    const float cx = child_xyz[((size_t)b * MPT + j) * 3 + 0];
    const float cy = child_xyz[((size_t)b * MPT + j) * 3 + 1];
    const float cz = child_xyz[((size_t)b * MPT + j) * 3 + 2];

    int cnt = 0;
    for (int base = 0; base < NPT; base += 32) {
        const int p = base + lane;
        const float dx = __fsub_rn(X[3 * p + 0], cx);
        const float dy = __fsub_rn(X[3 * p + 1], cy);
        const float dz = __fsub_rn(X[3 * p + 2], cz);
        const float cheap = cheap_d2(dx, dy, dz);
        bool in = (cheap <= R2LO);                         // certified in
        if (cheap > R2LO && cheap <= R2HI)                 // boundary band
            in = (dist2_acc(dx, dy, dz) <= R2C);
        const unsigned mask = __ballot_sync(FULLM, in);
        const int pos = cnt + __popc(mask & ((1u << lane) - 1u));
        if (in && pos < KNN) nidx[w][pos] = p;
        cnt += __popc(mask);
        if (cnt >= KNN) break;   // warp-uniform
    }
    if (cnt == 0) { if (lane == 0) nidx[w][0] = 0; cnt = 1; }
    const int kmax = cnt < KNN ? cnt : KNN;
    __syncwarp();

    const float* __restrict__ FT = g_feats_t + (size_t)b * NPT * CH;
    float m0 = -3.4e38f, m1 = -3.4e38f;
    for (int k = 0; k < kmax; k++) {
        const int p = nidx[w][k];                 // LDS broadcast
        const float2 v = *(const float2*)(FT + (size_t)p * CH + lane * 2);
        m0 = fmaxf(m0, v.x);
        m1 = fmaxf(m1, v.y);
    }
    sfeat[lane * 2 + 0][w] = m0;
    sfeat[lane * 2 + 1][w] = m1;
    __syncthreads();

    // coalesced staged store of (C x BQW) block
    for (int t = threadIdx.x; t < CH * BQW; t += BQW * 32) {
        const int c  = t >> 3;          // / BQW
        const int jj = t & (BQW - 1);
        out_feats[((size_t)b * CH + c) * MPT + j0 + jj] = sfeat[c][jj];
    }
}

// ---------------------------------------------------------------------------
extern "C" void kernel_launch(void* const* d_in, const int* in_sizes, int n_in,
                              void* d_out, int out_size)
{
    const float* xyz   = (const float*)d_in[0];
    const float* feats = (const float*)d_in[1];

    float* out         = (float*)d_out;
    float* child_xyz   = out;                              // (bs, m, 3)
    float* child_feats = out + (size_t)BS * MPT * 3;       // (bs, C, m)

    sort_kernel<<<BS, FPS_T>>>(xyz);
    transpose_kernel<<<dim3(NPT / 32, CH / 32, BS), dim3(32, 8)>>>(feats);
    fps_kernel<<<BS, FPS_T>>>(child_xyz);
    bq_group_kernel<<<dim3(MPT / BQW, BS), BQW * 32>>>(xyz, child_xyz, child_feats);
}

// round 14
// speedup vs baseline: 1.1912x; 1.0127x over previous
#include <cuda_runtime.h>
#include <cuda_bf16.h>

// Problem shapes (fixed for this registry entry)
#define BS  4
#define NPT 8192
#define CH  64
#define MPT 4096
#define KNN 32
#define R2C  0.04f
#define R2LO 0.03999996f   // R2*(1-1e-6): cheap <= R2LO  => faithful <= R2
#define R2HI 0.04000004f   // R2*(1+1e-6): cheap >  R2HI  => faithful >  R2

#define FPS_T 1024
#define PPT   (NPT / FPS_T)   // 8 points per thread (one spatial group)
#define BQW   8               // children (warps) per ball-query block
#define FULLM 0xffffffffu
#define NBIN  4096             // 16^3 Morton bins

typedef unsigned long long u64;

// Scratch
__device__ float  g_feats_t[(size_t)BS * NPT * CH];   // transposed feats, 8 MB
__device__ float4 g_sorted[(size_t)BS * NPT];         // Morton-sorted xyz+idx
__device__ unsigned g_code[(size_t)BS * NPT];         // per-point bin code

// ---------------------------------------------------------------------------
// Faithfully-rounded dx^2+dy^2+dz^2 via error-free transforms (f32 FMA pipe).
// Bit-exact selection behavior established in R3 (rel_err == 0).
// ---------------------------------------------------------------------------
__device__ __forceinline__ float dist2_acc(float dx, float dy, float dz)
{
    const float p1 = __fmul_rn(dx, dx);
    const float e1 = __fmaf_rn(dx, dx, -p1);
    const float p2 = __fmul_rn(dy, dy);
    const float e2 = __fmaf_rn(dy, dy, -p2);
    const float p3 = __fmul_rn(dz, dz);
    const float e3 = __fmaf_rn(dz, dz, -p3);
    const float s1  = __fadd_rn(p1, p2);
    const float b1  = __fsub_rn(s1, p1);
    const float t1  = __fadd_rn(__fsub_rn(p1, __fsub_rn(s1, b1)), __fsub_rn(p2, b1));
    const float s2  = __fadd_rn(s1, p3);
    const float b2  = __fsub_rn(s2, s1);
    const float t2  = __fadd_rn(__fsub_rn(s1, __fsub_rn(s2, b2)), __fsub_rn(p3, b2));
    const float err = __fadd_rn(__fadd_rn(__fadd_rn(e1, e2), e3), __fadd_rn(t1, t2));
    return __fadd_rn(s2, err);
}

__device__ __forceinline__ float cheap_d2(float dx, float dy, float dz)
{
    return __fmaf_rn(dz, dz, __fmaf_rn(dy, dy, __fmul_rn(dx, dx)));
}

// packed argmax key: high 32 = d2 bits (d2 >= 0 so order-preserving),
// low 32 = ~idx  =>  max key == max d2 with lowest-index tie-break.
__device__ __forceinline__ u64 pack_key(float v, unsigned idx)
{
    return ((u64)__float_as_uint(v) << 32) | (unsigned)(~idx);
}

// 4-bit spread for Morton: bit i -> bit 3i
__device__ __forceinline__ unsigned spread4(unsigned v)
{
    return (v & 1u) | ((v & 2u) << 2) | ((v & 4u) << 4) | ((v & 8u) << 6);
}
__device__ __forceinline__ unsigned morton12(float x, float y, float z)
{
    int qx = (int)floorf((x + 4.0f) * 2.0f);
    int qy = (int)floorf((y + 4.0f) * 2.0f);
    int qz = (int)floorf((z + 4.0f) * 2.0f);
    qx = min(15, max(0, qx)); qy = min(15, max(0, qy)); qz = min(15, max(0, qz));
    return spread4((unsigned)qx) | (spread4((unsigned)qy) << 1)
         | (spread4((unsigned)qz) << 2);
}

// ---------------------------------------------------------------------------
// Counting sort by 12-bit Morton code. One CTA per batch.
// Within-bin order is arbitrary (atomics) — grouping only affects pruning,
// never the FPS selection, so the final output is deterministic.
// ---------------------------------------------------------------------------
__global__ void __launch_bounds__(FPS_T, 1)
sort_kernel(const float* __restrict__ xyz)
{
    __shared__ unsigned hist[NBIN];
    __shared__ unsigned warpsum[32];

    const int b    = blockIdx.x;
    const int tid  = threadIdx.x;
    const int lane = tid & 31;
    const int wid  = tid >> 5;

    const float* __restrict__ X = xyz + (size_t)b * NPT * 3;

#pragma unroll
    for (int k = 0; k < NBIN / FPS_T; k++) hist[tid + k * FPS_T] = 0u;
    __syncthreads();

    // pass 1: codes + histogram
#pragma unroll
    for (int k = 0; k < PPT; k++) {
        const int j = tid + k * FPS_T;
        const unsigned code = morton12(X[3 * j], X[3 * j + 1], X[3 * j + 2]);
        g_code[(size_t)b * NPT + j] = code;
        atomicAdd(&hist[code], 1u);
    }
    __syncthreads();

    // exclusive prefix sum over 4096 bins (4 per thread)
    const unsigned c0 = hist[4 * tid + 0];
    const unsigned c1 = hist[4 * tid + 1];
    const unsigned c2 = hist[4 * tid + 2];
    const unsigned c3 = hist[4 * tid + 3];
    const unsigned tot = c0 + c1 + c2 + c3;
    unsigned incl = tot;
#pragma unroll
    for (int off = 1; off < 32; off <<= 1) {
        const unsigned n = __shfl_up_sync(FULLM, incl, off);
        if (lane >= off) incl += n;
    }
    if (lane == 31) warpsum[wid] = incl;
    __syncthreads();
    if (wid == 0) {
        const unsigned v = warpsum[lane];
        unsigned i2 = v;
#pragma unroll
        for (int off = 1; off < 32; off <<= 1) {
            const unsigned n = __shfl_up_sync(FULLM, i2, off);
            if (lane >= off) i2 += n;
        }
        warpsum[lane] = i2 - v;          // exclusive warp base
    }
    __syncthreads();
    unsigned base = warpsum[wid] + incl - tot;
    hist[4 * tid + 0] = base;  base += c0;
    hist[4 * tid + 1] = base;  base += c1;
    hist[4 * tid + 2] = base;  base += c2;
    hist[4 * tid + 3] = base;
    __syncthreads();

    // pass 2: scatter
#pragma unroll
    for (int k = 0; k < PPT; k++) {
        const int j = tid + k * FPS_T;
        const unsigned code = g_code[(size_t)b * NPT + j];
        const unsigned pos  = atomicAdd(&hist[code], 1u);
        float4 v;
        v.x = X[3 * j];  v.y = X[3 * j + 1];  v.z = X[3 * j + 2];
        v.w = __uint_as_float((unsigned)j);
        g_sorted[(size_t)b * NPT + pos] = v;
    }
}

// ---------------------------------------------------------------------------
// FPS: one CTA per batch, triangle-inequality group pruning, ALL register-
// resident (points loaded from the sorted array ONCE at init).
//  - thread owns 8 consecutive Morton-sorted points: centroid g, radius rt
//  - steady state: ONE cheap d2(c,g) vs S2; skip certifies no md update
//  - unpruned path: R9 per-slot certified filter + EFT (bit-exact)
//  - dirty-warp stage1 + redux argmax + coords-in-slots (R9 tail)
// ---------------------------------------------------------------------------
__global__ void __launch_bounds__(FPS_T, 1)
fps_kernel(float* __restrict__ child_xyz)
{
    __shared__ u64   skey[2][32];
    __shared__ float sx[2][32], sy[2][32], sz[2][32];
    __shared__ float c0s[3];

    const int b    = blockIdx.x;
    const int tid  = threadIdx.x;
    const int lane = tid & 31;
    const int wid  = tid >> 5;

    const float4* __restrict__ SP = g_sorted + (size_t)b * NPT;
    float* __restrict__        OX = child_xyz + (size_t)b * MPT * 3;

    // ---- init: load group into registers, compute stats ----
    float px[PPT], py[PPT], pz[PPT], md[PPT];
    unsigned oid[PPT];
    float gx = 0.f, gy = 0.f, gz = 0.f;
#pragma unroll
    for (int k = 0; k < PPT; k++) {
        const float4 p = __ldg(&SP[tid * PPT + k]);
        px[k] = p.x; py[k] = p.y; pz[k] = p.z;
        oid[k] = __float_as_uint(p.w);
        md[k] = 1e10f;
        gx += p.x; gy += p.y; gz += p.z;
        if (oid[k] == 0u) { c0s[0] = p.x; c0s[1] = p.y; c0s[2] = p.z; }
    }
    gx *= 0.125f; gy *= 0.125f; gz *= 0.125f;

    float r2m = 0.f;
    u64   ckey = 0;
    float ax = 0.f, ay = 0.f, az = 0.f;
#pragma unroll
    for (int k = 0; k < PPT; k++) {
        r2m = fmaxf(r2m, cheap_d2(px[k] - gx, py[k] - gy, pz[k] - gz));
        const u64 key = pack_key(1e10f, oid[k]);
        if (key > ckey) { ckey = key; ax = px[k]; ay = py[k]; az = pz[k]; }
    }
    const float rt = __fsqrt_ru(__fmul_ru(r2m, 1.00001f));  // certified ub
    float S2;
    {
        const float S = __fadd_ru(__fsqrt_ru(1e10f), rt);
        S2 = __fmul_ru(__fmul_ru(S, S), 1.00001f);          // always pass at it=0
    }

    // warp-best cache (held by all lanes; lane0 reposts it each iter)
    u64   wkey = 0;
    float wx = 0.f, wy = 0.f, wz = 0.f;

    __syncthreads();
    float cx = c0s[0], cy = c0s[1], cz = c0s[2];

    for (int it = 0; it < MPT; it++) {
        if (tid == 0) {
            OX[3 * it + 0] = cx;
            OX[3 * it + 1] = cy;
            OX[3 * it + 2] = cz;
        }

        // ---- group prune test (steady state: this is ALL the work) ----
        const float d2g = cheap_d2(gx - cx, gy - cy, gz - cz);
        bool updated = false;
        if (d2g <= S2) {                      // group cannot be pruned
#pragma unroll
            for (int k = 0; k < PPT; k++) {
                const float dx = __fsub_rn(px[k], cx);
                const float dy = __fsub_rn(py[k], cy);
                const float dz = __fsub_rn(pz[k], cz);
                const float cheap = cheap_d2(dx, dy, dz);
                if (cheap <= __fmul_rn(md[k], 1.000001f)) {   // R9 filter
                    const float d2 = dist2_acc(dx, dy, dz);
                    if (d2 < md[k]) { md[k] = d2; updated = true; }
                }
            }
        }
        if (updated) {                        // rare: refresh caches
            u64 nk = pack_key(md[0], oid[0]);
            int bs = 0;
#pragma unroll
            for (int k = 1; k < PPT; k++) {
                const u64 key = pack_key(md[k], oid[k]);
                if (key > nk) { nk = key; bs = k; }
            }
            ckey = nk;
            ax = px[bs]; ay = py[bs]; az = pz[bs];
            const float Mk = __uint_as_float((unsigned)(nk >> 32)); // max md
            const float S  = __fadd_ru(__fsqrt_ru(Mk), rt);
            S2 = __fmul_ru(__fmul_ru(S, S), 1.00001f);
        }

        // stage1: only dirty warps re-reduce (md monotone non-increasing)
        const unsigned dirty = __ballot_sync(FULLM, updated);
        if (dirty) {
            const unsigned hi = (unsigned)(ckey >> 32);
            const unsigned lo = (unsigned)ckey;
            const unsigned mh = __reduce_max_sync(FULLM, hi);
            const unsigned ml = __reduce_max_sync(FULLM, (hi == mh) ? lo : 0u);
            wkey = ((u64)mh << 32) | ml;
            const bool win = (hi == mh) && (lo == ml);   // unique lane
            const int  wl  = __ffs(__ballot_sync(FULLM, win)) - 1;
            wx = __shfl_sync(FULLM, ax, wl);
            wy = __shfl_sync(FULLM, ay, wl);
            wz = __shfl_sync(FULLM, az, wl);
        }
        const int p = it & 1;
        if (lane == 0) {
            skey[p][wid] = wkey;
            sx[p][wid] = wx; sy[p][wid] = wy; sz[p][wid] = wz;
        }
        __syncthreads();

        // stage2: every warp reduces the 32 per-warp slots via redux
        const u64 k2       = skey[p][lane];
        const unsigned hi2 = (unsigned)(k2 >> 32);
        const unsigned lo2 = (unsigned)k2;
        const unsigned mh2 = __reduce_max_sync(FULLM, hi2);
        const unsigned ml2 = __reduce_max_sync(FULLM, (hi2 == mh2) ? lo2 : 0u);
        const bool match   = (hi2 == mh2) && (lo2 == ml2);
        const int  s       = __ffs(__ballot_sync(FULLM, match)) - 1;
        cx = sx[p][s]; cy = sy[p][s]; cz = sz[p][s];      // broadcast LDS
    }
}

// ---------------------------------------------------------------------------
// Transpose feats (bs, C, N) -> g_feats_t (bs, N, C), tiled 32x32.
// ---------------------------------------------------------------------------
__global__ void transpose_kernel(const float* __restrict__ feats)
{
    __shared__ float tile[32][33];
    const int b  = blockIdx.z;
    const int n0 = blockIdx.x * 32;
    const int c0 = blockIdx.y * 32;
    const int tx = threadIdx.x;
    const int ty = threadIdx.y;

    const float* __restrict__ F  = feats + (size_t)b * CH * NPT;
    float* __restrict__       FT = g_feats_t + (size_t)b * NPT * CH;

#pragma unroll
    for (int r = ty; r < 32; r += 8)
        tile[r][tx] = F[(size_t)(c0 + r) * NPT + n0 + tx];
    __syncthreads();
#pragma unroll
    for (int r = ty; r < 32; r += 8)
        FT[(size_t)(n0 + r) * CH + c0 + tx] = tile[tx][r];
}

// ---------------------------------------------------------------------------
// Fused ball query (first-K-within-radius, ascending index) + grouped max.
// Certified cheap filter: EFT only in the 1e-6-wide boundary band.
// ---------------------------------------------------------------------------
__global__ void __launch_bounds__(BQW * 32)
bq_group_kernel(const float* __restrict__ xyz,
                const float* __restrict__ child_xyz,
                float* __restrict__ out_feats)
{
    __shared__ int   nidx[BQW][KNN];
    __shared__ float sfeat[CH][BQW];

    const int b    = blockIdx.y;
    const int j0   = blockIdx.x * BQW;
    const int w    = threadIdx.x >> 5;
    const int lane = threadIdx.x & 31;
    const int j    = j0 + w;

    const float* __restrict__ X = xyz + (size_t)b * NPT * 3;
    const float cx = child_xyz[((size_t)b * MPT + j) * 3 + 0];
    const float cy = child_xyz[((size_t)b * MPT + j) * 3 + 1];
    const float cz = child_xyz[((size_t)b * MPT + j) * 3 + 2];

    int cnt = 0;
    for (int base = 0; base < NPT; base += 32) {
        const int p = base + lane;
        const float dx = __fsub_rn(X[3 * p + 0], cx);
        const float dy = __fsub_rn(X[3 * p + 1], cy);
        const float dz = __fsub_rn(X[3 * p + 2], cz);
        const float cheap = cheap_d2(dx, dy, dz);
        bool in = (cheap <= R2LO);                         // certified in
        if (cheap > R2LO && cheap <= R2HI)                 // boundary band
            in = (dist2_acc(dx, dy, dz) <= R2C);
        const unsigned mask = __ballot_sync(FULLM, in);
        const int pos = cnt + __popc(mask & ((1u << lane) - 1u));
        if (in && pos < KNN) nidx[w][pos] = p;
        cnt += __popc(mask);
        if (cnt >= KNN) break;   // warp-uniform
    }
    if (cnt == 0) { if (lane == 0) nidx[w][0] = 0; cnt = 1; }
    const int kmax = cnt < KNN ? cnt : KNN;
    __syncwarp();

    const float* __restrict__ FT = g_feats_t + (size_t)b * NPT * CH;
    float m0 = -3.4e38f, m1 = -3.4e38f;
    for (int k = 0; k < kmax; k++) {
        const int p = nidx[w][k];                 // LDS broadcast
        const float2 v = *(const float2*)(FT + (size_t)p * CH + lane * 2);
        m0 = fmaxf(m0, v.x);
        m1 = fmaxf(m1, v.y);
    }
    sfeat[lane * 2 + 0][w] = m0;
    sfeat[lane * 2 + 1][w] = m1;
    __syncthreads();

    // coalesced staged store of (C x BQW) block
    for (int t = threadIdx.x; t < CH * BQW; t += BQW * 32) {
        const int c  = t >> 3;          // / BQW
        const int jj = t & (BQW - 1);
        out_feats[((size_t)b * CH + c) * MPT + j0 + jj] = sfeat[c][jj];
    }
}

// ---------------------------------------------------------------------------
extern "C" void kernel_launch(void* const* d_in, const int* in_sizes, int n_in,
                              void* d_out, int out_size)
{
    const float* xyz   = (const float*)d_in[0];
    const float* feats = (const float*)d_in[1];

    float* out         = (float*)d_out;
    float* child_xyz   = out;                              // (bs, m, 3)
    float* child_feats = out + (size_t)BS * MPT * 3;       // (bs, C, m)

    sort_kernel<<<BS, FPS_T>>>(xyz);
    transpose_kernel<<<dim3(NPT / 32, CH / 32, BS), dim3(32, 8)>>>(feats);
    fps_kernel<<<BS, FPS_T>>>(child_xyz);
    bq_group_kernel<<<dim3(MPT / BQW, BS), BQW * 32>>>(xyz, child_xyz, child_feats);
}

// round 17
// speedup vs baseline: 1.3769x; 1.1559x over previous
#include <cuda_runtime.h>
#include <cuda_bf16.h>

// Problem shapes (fixed for this registry entry)
#define BS  4
#define NPT 8192
#define CH  64
#define MPT 4096
#define KNN 32
#define R2C  0.04f
#define R2LO 0.03999996f   // R2*(1-1e-6): cheap <= R2LO  => faithful <= R2
#define R2HI 0.04000004f   // R2*(1+1e-6): cheap >  R2HI  => faithful >  R2

// absolute certification margin for the expanded-norm filter (|p|,|c| <= ~6):
// total rounding error of q + nc vs true d2 is <= ~3.5e-5 << 1e-4
#define FMARGIN 1e-4f

#define FPS_T 512
#define PPT   (NPT / FPS_T)   // 16 points per thread
#define NWARP (FPS_T / 32)    // 16 warps
#define BQW   8               // children (warps) per ball-query block
#define FULLM 0xffffffffu

typedef unsigned long long u64;

// Scratch: transposed feats (bs, n, c). 8 MB.
__device__ float g_feats_t[(size_t)BS * NPT * CH];

// ---------------------------------------------------------------------------
// Faithfully-rounded dx^2+dy^2+dz^2 via error-free transforms (f32 FMA pipe).
// Bit-exact selection behavior established in R3 (rel_err == 0).
// ---------------------------------------------------------------------------
__device__ __forceinline__ float dist2_acc(float dx, float dy, float dz)
{
    const float p1 = __fmul_rn(dx, dx);
    const float e1 = __fmaf_rn(dx, dx, -p1);
    const float p2 = __fmul_rn(dy, dy);
    const float e2 = __fmaf_rn(dy, dy, -p2);
    const float p3 = __fmul_rn(dz, dz);
    const float e3 = __fmaf_rn(dz, dz, -p3);
    const float s1  = __fadd_rn(p1, p2);
    const float b1  = __fsub_rn(s1, p1);
    const float t1  = __fadd_rn(__fsub_rn(p1, __fsub_rn(s1, b1)), __fsub_rn(p2, b1));
    const float s2  = __fadd_rn(s1, p3);
    const float b2  = __fsub_rn(s2, s1);
    const float t2  = __fadd_rn(__fsub_rn(s1, __fsub_rn(s2, b2)), __fsub_rn(p3, b2));
    const float err = __fadd_rn(__fadd_rn(__fadd_rn(e1, e2), e3), __fadd_rn(t1, t2));
    return __fadd_rn(s2, err);
}

__device__ __forceinline__ float cheap_d2(float dx, float dy, float dz)
{
    return __fmaf_rn(dz, dz, __fmaf_rn(dy, dy, __fmul_rn(dx, dx)));
}

// packed argmax key: high 32 = d2 bits (d2 >= 0 so order-preserving),
// low 32 = ~idx  =>  max key == max d2 with lowest-index tie-break.
__device__ __forceinline__ u64 pack_key(float v, int idx)
{
    return ((u64)__float_as_uint(v) << 32) | (unsigned)(~idx);
}

// ---------------------------------------------------------------------------
// FPS: one CTA per batch, 512 threads x 16 points (128-reg budget, NO spills).
//  - expanded-norm 4-op certified filter (q vs md + FMARGIN - |c|^2)
//  - per-slot rare branch to bit-exact EFT (R9 structure)
//  - dirty-warp stage1 + redux argmax + coords-in-slots, one barrier/iter
// ---------------------------------------------------------------------------
__global__ void __launch_bounds__(FPS_T, 1)
fps_kernel(const float* __restrict__ xyz, float* __restrict__ child_xyz)
{
    __shared__ u64   skey[2][32];
    __shared__ float sx[2][32], sy[2][32], sz[2][32];

    const int b    = blockIdx.x;
    const int tid  = threadIdx.x;
    const int lane = tid & 31;
    const int wid  = tid >> 5;

    const float* __restrict__ X  = xyz + (size_t)b * NPT * 3;
    float* __restrict__       OX = child_xyz + (size_t)b * MPT * 3;

    // zero the unused stage2 slots (lanes 16..31) for both parities
    if (tid < 64) ((u64*)skey)[tid] = 0;

    float px[PPT], py[PPT], pz[PPT], np[PPT], md[PPT];
#pragma unroll
    for (int k = 0; k < PPT; k++) {
        const int j = tid + k * FPS_T;
        px[k] = X[3 * j + 0];
        py[k] = X[3 * j + 1];
        pz[k] = X[3 * j + 2];
        np[k] = cheap_d2(px[k], py[k], pz[k]);   // |p|^2, 3 roundings
        md[k] = 1e10f;
    }
    // thread-best cache (all md equal -> k=0 -> lowest idx = tid)
    u64   ckey = pack_key(1e10f, tid);
    float ax = px[0], ay = py[0], az = pz[0];
    // warp-best cache (held by all lanes; lane0 reposts it each iter)
    u64   wkey = 0;
    float wx = 0.f, wy = 0.f, wz = 0.f;

    float cx = X[0], cy = X[1], cz = X[2];
    __syncthreads();

    for (int it = 0; it < MPT; it++) {
        if (tid == 0) {
            OX[3 * it + 0] = cx;
            OX[3 * it + 1] = cy;
            OX[3 * it + 2] = cz;
        }
        // per-iteration constants (exact *2 negate; e carries the margin)
        const float ca = -2.0f * cx;
        const float cb = -2.0f * cy;
        const float cc = -2.0f * cz;
        const float nc = cheap_d2(cx, cy, cz);
        const float e  = __fsub_rn(FMARGIN, nc);

        bool updated = false;
#pragma unroll
        for (int k = 0; k < PPT; k++) {
            // q ~= |p|^2 - 2 p.c ; q + nc ~= d2 within ~3.5e-5 (certified)
            const float q   = __fmaf_rn(px[k], ca, __fmaf_rn(py[k], cb,
                              __fmaf_rn(pz[k], cc, np[k])));
            const float rhs = __fadd_rn(md[k], e);
            if (q <= rhs) {                              // rare (certified)
                const float dx = __fsub_rn(px[k], cx);
                const float dy = __fsub_rn(py[k], cy);
                const float dz = __fsub_rn(pz[k], cz);
                const float d2 = dist2_acc(dx, dy, dz);
                if (d2 < md[k]) { md[k] = d2; updated = true; }
            }
        }

        // stage1: only dirty warps re-reduce (md monotone non-increasing)
        const unsigned dirty = __ballot_sync(FULLM, updated);
        if (dirty) {
            if (updated) {                      // refresh thread cache
                float bv = md[0]; int bi = tid;
                float tx = px[0], ty = py[0], tz = pz[0];
#pragma unroll
                for (int k = 1; k < PPT; k++)
                    if (md[k] > bv) {
                        bv = md[k]; bi = tid + k * FPS_T;
                        tx = px[k]; ty = py[k]; tz = pz[k];
                    }
                ckey = pack_key(bv, bi);
                ax = tx; ay = ty; az = tz;
            }
            const unsigned hi = (unsigned)(ckey >> 32);
            const unsigned lo = (unsigned)ckey;
            const unsigned mh = __reduce_max_sync(FULLM, hi);
            const unsigned ml = __reduce_max_sync(FULLM, (hi == mh) ? lo : 0u);
            wkey = ((u64)mh << 32) | ml;
            const bool win = (hi == mh) && (lo == ml);   // unique lane
            const int  wl  = __ffs(__ballot_sync(FULLM, win)) - 1;
            wx = __shfl_sync(FULLM, ax, wl);
            wy = __shfl_sync(FULLM, ay, wl);
            wz = __shfl_sync(FULLM, az, wl);
        }
        const int p = it & 1;
        if (lane == 0) {
            skey[p][wid] = wkey;
            sx[p][wid] = wx; sy[p][wid] = wy; sz[p][wid] = wz;
        }
        __syncthreads();

        // stage2: every warp reduces the 16 per-warp slots (16..31 are 0)
        const u64 k2       = skey[p][lane];
        const unsigned hi2 = (unsigned)(k2 >> 32);
        const unsigned lo2 = (unsigned)k2;
        const unsigned mh2 = __reduce_max_sync(FULLM, hi2);
        const unsigned ml2 = __reduce_max_sync(FULLM, (hi2 == mh2) ? lo2 : 0u);
        const bool match   = (hi2 == mh2) && (lo2 == ml2);
        const int  s       = __ffs(__ballot_sync(FULLM, match)) - 1;
        cx = sx[p][s]; cy = sy[p][s]; cz = sz[p][s];      // broadcast LDS
    }
}

// ---------------------------------------------------------------------------
// Transpose feats (bs, C, N) -> g_feats_t (bs, N, C), tiled 32x32.
// ---------------------------------------------------------------------------
__global__ void transpose_kernel(const float* __restrict__ feats)
{
    __shared__ float tile[32][33];
    const int b  = blockIdx.z;
    const int n0 = blockIdx.x * 32;
    const int c0 = blockIdx.y * 32;
    const int tx = threadIdx.x;
    const int ty = threadIdx.y;

    const float* __restrict__ F  = feats + (size_t)b * CH * NPT;
    float* __restrict__       FT = g_feats_t + (size_t)b * NPT * CH;

#pragma unroll
    for (int r = ty; r < 32; r += 8)
        tile[r][tx] = F[(size_t)(c0 + r) * NPT + n0 + tx];
    __syncthreads();
#pragma unroll
    for (int r = ty; r < 32; r += 8)
        FT[(size_t)(n0 + r) * CH + c0 + tx] = tile[tx][r];
}

// ---------------------------------------------------------------------------
// Fused ball query (first-K-within-radius, ascending index) + grouped max.
// Certified cheap filter: EFT only in the 1e-6-wide boundary band.
// ---------------------------------------------------------------------------
__global__ void __launch_bounds__(BQW * 32)
bq_group_kernel(const float* __restrict__ xyz,
                const float* __restrict__ child_xyz,
                float* __restrict__ out_feats)
{
    __shared__ int   nidx[BQW][KNN];
    __shared__ float sfeat[CH][BQW];

    const int b    = blockIdx.y;
    const int j0   = blockIdx.x * BQW;
    const int w    = threadIdx.x >> 5;
    const int lane = threadIdx.x & 31;
    const int j    = j0 + w;

    const float* __restrict__ X = xyz + (size_t)b * NPT * 3;
    const float cx = child_xyz[((size_t)b * MPT + j) * 3 + 0];
    const float cy = child_xyz[((size_t)b * MPT + j) * 3 + 1];
    const float cz = child_xyz[((size_t)b * MPT + j) * 3 + 2];

    int cnt = 0;
    for (int base = 0; base < NPT; base += 32) {
        const int p = base + lane;
        const float dx = __fsub_rn(X[3 * p + 0], cx);
        const float dy = __fsub_rn(X[3 * p + 1], cy);
        const float dz = __fsub_rn(X[3 * p + 2], cz);
        const float cheap = cheap_d2(dx, dy, dz);
        bool in = (cheap <= R2LO);                         // certified in
        if (cheap > R2LO && cheap <= R2HI)                 // boundary band
            in = (dist2_acc(dx, dy, dz) <= R2C);
        const unsigned mask = __ballot_sync(FULLM, in);
        const int pos = cnt + __popc(mask & ((1u << lane) - 1u));
        if (in && pos < KNN) nidx[w][pos] = p;
        cnt += __popc(mask);
        if (cnt >= KNN) break;   // warp-uniform
    }
    if (cnt == 0) { if (lane == 0) nidx[w][0] = 0; cnt = 1; }
    const int kmax = cnt < KNN ? cnt : KNN;
    __syncwarp();

    const float* __restrict__ FT = g_feats_t + (size_t)b * NPT * CH;
    float m0 = -3.4e38f, m1 = -3.4e38f;
    for (int k = 0; k < kmax; k++) {
        const int p = nidx[w][k];                 // LDS broadcast
        const float2 v = *(const float2*)(FT + (size_t)p * CH + lane * 2);
        m0 = fmaxf(m0, v.x);
        m1 = fmaxf(m1, v.y);
    }
    sfeat[lane * 2 + 0][w] = m0;
    sfeat[lane * 2 + 1][w] = m1;
    __syncthreads();

    // coalesced staged store of (C x BQW) block
    for (int t = threadIdx.x; t < CH * BQW; t += BQW * 32) {
        const int c  = t >> 3;          // / BQW
        const int jj = t & (BQW - 1);
        out_feats[((size_t)b * CH + c) * MPT + j0 + jj] = sfeat[c][jj];
    }
}

// ---------------------------------------------------------------------------
extern "C" void kernel_launch(void* const* d_in, const int* in_sizes, int n_in,
                              void* d_out, int out_size)
{
    const float* xyz   = (const float*)d_in[0];
    const float* feats = (const float*)d_in[1];

    float* out         = (float*)d_out;
    float* child_xyz   = out;                              // (bs, m, 3)
    float* child_feats = out + (size_t)BS * MPT * 3;       // (bs, C, m)

    transpose_kernel<<<dim3(NPT / 32, CH / 32, BS), dim3(32, 8)>>>(feats);
    fps_kernel<<<BS, FPS_T>>>(xyz, child_xyz);
    bq_group_kernel<<<dim3(MPT / BQW, BS), BQW * 32>>>(xyz, child_xyz, child_feats);
}